// round 7
// baseline (speedup 1.0000x reference)
#include <cuda_runtime.h>
#include <cuda_bf16.h>

// SurfEval: single fused kernel, occupancy-optimized.
// B=16, M=N=64, deg=3, OUT=256x256, out dim 3 (ctrl has 4 ch, w unused).
// Reference quirks preserved:
//   * V basis is built from knot_u (knot_v is a dead input) -> Nv==Nu, vspan==uspan.
//   * span = argmin over cand = (t-K[3+s] > 1e-8) ? d : 1.0, first-min tie-break.
//     U strictly increasing => argmin = largest s with d > 1e-8 (0 if none)
//     => 6-step binary search, identical result.
//   * Cox-de Boor denominator written as (K1 - t) + (t - K2).
//   * cumsum: thread-0 sequential adds in reference order over SMEM (unrolled),
//     after a cooperative coalesced global stage. Bit-identical FP result.
//
// Eval: surf(u,v) = sum_l nu[l]*S_{iu0+l}(v), S_m(v) = sum_r nv[r]*ctrl[m][iv0+r].
// Block = (u-tile of 4, batch); thread = v. 4-entry register ring of S_m slides
// across the 4 u rows. TILE_U=4 -> 1024 blocks = 8192 warps (86% of chip slots);
// __launch_bounds__(256,7) keeps 7 blocks resident per SM.
// u-weights are stored PRE-ROTATED by ring slot: nub[uu][(iu0+l)&3] = nu[l],
// so the hot loop uses slot-direct weights with zero index arithmetic.

#define BSZ    16
#define MC     64
#define NC     64
#define DEG    3
#define LK     (MC + DEG + 1)   // 68
#define OUTN   256
#define TILE_U 4                // grid.x = 64 -> 1024 blocks
#define WROWS  16               // compact ctrl window capacity (16 KB)

__device__ __forceinline__ float param_t(int idx)
{
    const float step = (1.0f - 2e-5f) / (float)(OUTN - 1);
    return 1e-5f + (float)idx * step;
}

// find_span (binary search, equivalent to reference argmin) + Cox-de Boor.
__device__ __forceinline__ void basis_at(float t, const float* __restrict__ U,
                                         float nb[4], int* iu0_out)
{
    int lo = 0, hi = LK - 2 * DEG - 1;           // s in [0, 61]
    if (!(t - U[DEG] > 1e-8f)) {
        lo = 0;
    } else {
        #pragma unroll
        for (int step = 0; step < 6; step++) {   // ceil(log2(62)) = 6
            if (lo < hi) {
                const int mid = (lo + hi + 1) >> 1;
                if (t - U[DEG + mid] > 1e-8f) lo = mid; else hi = mid - 1;
            }
        }
    }
    const int span = lo + DEG;

    nb[0] = 1.0f; nb[1] = 0.f; nb[2] = 0.f; nb[3] = 0.f;
    #pragma unroll
    for (int k = 1; k <= DEG; k++) {
        float saved = 0.0f;
        #pragma unroll
        for (int r = 0; r < k; r++) {
            const float K1 = U[span + r + 1];
            const float K2 = U[span + 1 - k + r];
            const float temp = nb[r] / ((K1 - t) + (t - K2));
            nb[r] = saved + (K1 - t) * temp;
            saved = (t - K2) * temp;
        }
        nb[k] = saved;
    }
    *iu0_out = span - DEG;
}

__global__ __launch_bounds__(256, 7)
void surfeval_fused(const float4* __restrict__ ctrl,
                    const float*  __restrict__ knot_u,
                    float* __restrict__ out)
{
    __shared__ float4 win[WROWS * NC];    // 16 KB compact ctrl window
    __shared__ float  U[LK];
    __shared__ float  nub[TILE_U][4];     // PRE-ROTATED: [uu][ring slot]
    __shared__ int    ius[TILE_U];
    __shared__ float  norm_c0, norm_inv;

    const int b   = blockIdx.y;
    const int u0  = blockIdx.x * TILE_U;
    const int tid = threadIdx.x;          // = v

    // ---- stage raw knots (coalesced, L2-hot) ----
    if (tid < LK) U[tid] = knot_u[b * LK + tid];
    __syncthreads();

    // ---- sequential cumsum over SMEM, fully unrolled (reference FP order) ----
    if (tid == 0) {
        float c = 0.f;
        #pragma unroll
        for (int j = 0; j < LK; j++) { c += U[j]; U[j] = c; }
        norm_c0  = U[0];
        norm_inv = 1.0f / (U[LK - 1] - U[0]);
    }
    __syncthreads();

    // ---- parallel normalize (per-element in-place, race-free) ----
    if (tid < LK) U[tid] = (U[tid] - norm_c0) * norm_inv;
    __syncthreads();

    // ---- basis for this thread's v ----
    float nv[4]; int iv0;
    basis_at(param_t(tid), U, nv, &iv0);
    const float nv0 = nv[0], nv1 = nv[1], nv2 = nv[2], nv3 = nv[3];

    // ---- basis for the tile's u rows, stored rotated by ring slot ----
    if (tid < TILE_U) {
        float nb[4]; int iu;
        basis_at(param_t(u0 + tid), U, nb, &iu);
        ius[tid] = iu;
        #pragma unroll
        for (int l = 0; l < 4; l++) nub[tid][(iu + l) & 3] = nb[l];
    }
    __syncthreads();

    // ---- window bounds (per-thread; TILE_U smem reads) ----
    int mlo = ius[0], mhi = ius[0];
    #pragma unroll
    for (int i = 1; i < TILE_U; i++) {
        mlo = min(mlo, ius[i]); mhi = max(mhi, ius[i]);
    }
    mhi += DEG;
    int nrows = mhi - mlo + 1;
    if (nrows > WROWS) nrows = WROWS;     // safety clamp (never hit here)

    // ---- cooperative compact window load: nrows*64 float4 (<= 2/thread) ----
    for (int idx = tid; idx < nrows * NC; idx += 256) {
        win[idx] = ctrl[((size_t)b * MC + mlo) * NC + idx];
    }
    __syncthreads();

    // ---- sliding-window evaluation over 4 u rows ----
    float3 S0, S1, S2, S3;                // ring slots, slot = m & 3
    int mtop = mlo - 1;                   // highest m with S computed

    float* op = out + (((size_t)(b * OUTN + u0) * OUTN) + tid) * 3;

    #pragma unroll 1
    for (int uu = 0; uu < TILE_U; uu++) {
        const int iu0 = ius[uu];
        if (mtop < iu0 - 1 || mtop > iu0 + 3) mtop = iu0 - 1;  // safety reseed
        while (mtop < iu0 + 3) {
            mtop++;
            const float4* wrow = &win[(mtop - mlo) * NC + iv0];
            const float4 c0 = wrow[0], c1 = wrow[1], c2 = wrow[2], c3 = wrow[3];
            float sx = fmaf(nv0, c0.x, fmaf(nv1, c1.x, fmaf(nv2, c2.x, nv3 * c3.x)));
            float sy = fmaf(nv0, c0.y, fmaf(nv1, c1.y, fmaf(nv2, c2.y, nv3 * c3.y)));
            float sz = fmaf(nv0, c0.z, fmaf(nv1, c1.z, fmaf(nv2, c2.z, nv3 * c3.z)));
            const int slot = mtop & 3;
            if      (slot == 0) S0 = make_float3(sx, sy, sz);
            else if (slot == 1) S1 = make_float3(sx, sy, sz);
            else if (slot == 2) S2 = make_float3(sx, sy, sz);
            else                S3 = make_float3(sx, sy, sz);
        }

        // slot-direct pre-rotated weights: no index arithmetic
        const float w0 = nub[uu][0];
        const float w1 = nub[uu][1];
        const float w2 = nub[uu][2];
        const float w3 = nub[uu][3];

        op[0] = fmaf(w0, S0.x, fmaf(w1, S1.x, fmaf(w2, S2.x, w3 * S3.x)));
        op[1] = fmaf(w0, S0.y, fmaf(w1, S1.y, fmaf(w2, S2.y, w3 * S3.y)));
        op[2] = fmaf(w0, S0.z, fmaf(w1, S1.z, fmaf(w2, S2.z, w3 * S3.z)));
        op += OUTN * 3;
    }
}

// ---------------------------------------------------------------------------
extern "C" void kernel_launch(void* const* d_in, const int* in_sizes, int n_in,
                              void* d_out, int out_size)
{
    const float4* ctrl   = (const float4*)d_in[0];   // [16,64,64,4] f32
    const float*  knot_u = (const float*)d_in[1];    // [16,68] f32
    // d_in[2] (knot_v) unused: reference builds V from knot_u
    float* out = (float*)d_out;                      // [16,256,256,3] f32

    dim3 grid(OUTN / TILE_U, BSZ);                   // 64 x 16 = 1024 blocks
    surfeval_fused<<<grid, 256>>>(ctrl, knot_u, out);
}

// round 8
// speedup vs baseline: 1.4810x; 1.4810x over previous
#include <cuda_runtime.h>
#include <cuda_bf16.h>

// SurfEval: single fused kernel (round-6 config + faster prologue).
// B=16, M=N=64, deg=3, OUT=256x256, out dim 3 (ctrl has 4 ch, w unused).
// Reference quirks preserved:
//   * V basis is built from knot_u (knot_v is a dead input) -> Nv==Nu, vspan==uspan.
//   * span = argmin over cand = (t-K[3+s] > 1e-8) ? d : 1.0, first-min tie-break.
//     U strictly increasing => argmin = largest s with d > 1e-8 (0 if none)
//     => 6-step binary search, identical result.
//   * Cox-de Boor denominator written as (K1 - t) + (t - K2).
//   * cumsum: parallel shuffle scan (reassociated FP; error ~1e-7 rel,
//     tolerance is 1e-3).
//
// Eval: surf(u,v) = sum_l nu[l]*S_{iu0+l}(v), S_m(v) = sum_r nv[r]*ctrl[m][iv0+r].
// Block = (u-tile of 8, batch); thread = v. 4-entry register ring of S_m slides
// across the 8 u rows (~6 S-computes per 8 outputs). u-weights pre-rotated by
// ring slot so the hot loop has zero weight-index arithmetic.

#define BSZ    16
#define MC     64
#define NC     64
#define DEG    3
#define LK     (MC + DEG + 1)   // 68
#define OUTN   256
#define TILE_U 8                // grid.x = 32 -> 512 blocks
#define WROWS  16               // compact ctrl window capacity (16 KB)

__device__ __forceinline__ float param_t(int idx)
{
    const float step = (1.0f - 2e-5f) / (float)(OUTN - 1);
    return 1e-5f + (float)idx * step;
}

// find_span (binary search, equivalent to reference argmin) + Cox-de Boor.
__device__ __forceinline__ void basis_at(float t, const float* __restrict__ U,
                                         float nb[4], int* iu0_out)
{
    int lo = 0, hi = LK - 2 * DEG - 1;           // s in [0, 61]
    if (!(t - U[DEG] > 1e-8f)) {
        lo = 0;
    } else {
        #pragma unroll
        for (int step = 0; step < 6; step++) {   // ceil(log2(62)) = 6
            if (lo < hi) {
                const int mid = (lo + hi + 1) >> 1;
                if (t - U[DEG + mid] > 1e-8f) lo = mid; else hi = mid - 1;
            }
        }
    }
    const int span = lo + DEG;

    nb[0] = 1.0f; nb[1] = 0.f; nb[2] = 0.f; nb[3] = 0.f;
    #pragma unroll
    for (int k = 1; k <= DEG; k++) {
        float saved = 0.0f;
        #pragma unroll
        for (int r = 0; r < k; r++) {
            const float K1 = U[span + r + 1];
            const float K2 = U[span + 1 - k + r];
            const float temp = nb[r] / ((K1 - t) + (t - K2));
            nb[r] = saved + (K1 - t) * temp;
            saved = (t - K2) * temp;
        }
        nb[k] = saved;
    }
    *iu0_out = span - DEG;
}

__global__ __launch_bounds__(256)
void surfeval_fused(const float4* __restrict__ ctrl,
                    const float*  __restrict__ knot_u,
                    float* __restrict__ out)
{
    __shared__ float4 win[WROWS * NC];    // 16 KB compact ctrl window
    __shared__ float  U[LK];
    __shared__ float  nub[TILE_U][4];     // PRE-ROTATED: [uu][ring slot]
    __shared__ int    ius[TILE_U];
    __shared__ float  warpsum[3];

    const int b    = blockIdx.y;
    const int u0   = blockIdx.x * TILE_U;
    const int tid  = threadIdx.x;         // = v
    const int lane = tid & 31;
    const int wid  = tid >> 5;

    // ---- stage raw knots (coalesced, L2-hot) ----
    if (tid < LK) U[tid] = knot_u[b * LK + tid];
    __syncthreads();

    // ---- parallel cumsum: warp shuffle scan over 68 elems (warps 0..2) ----
    const float c0 = U[0];                 // raw first knot (broadcast LDS)
    float val = 0.f;
    if (wid < 3) {
        if (tid < LK) val = U[tid];
        #pragma unroll
        for (int off = 1; off < 32; off <<= 1) {
            const float n = __shfl_up_sync(0xffffffffu, val, off);
            if (lane >= off) val += n;
        }
        if (lane == 31) warpsum[wid] = val;
    }
    __syncthreads();

    if (wid < 3) {
        float offset = 0.f;
        if (wid >= 1) offset += warpsum[0];
        if (wid >= 2) offset += warpsum[1];
        val += offset;
        const float total = warpsum[0] + warpsum[1] + warpsum[2];
        const float inv   = 1.0f / (total - c0);
        if (tid < LK) U[tid] = (val - c0) * inv;
    }
    __syncthreads();

    // ---- basis for this thread's v ----
    float nv[4]; int iv0;
    basis_at(param_t(tid), U, nv, &iv0);
    const float nv0 = nv[0], nv1 = nv[1], nv2 = nv[2], nv3 = nv[3];

    // ---- basis for the tile's u rows, stored rotated by ring slot ----
    if (tid < TILE_U) {
        float nb[4]; int iu;
        basis_at(param_t(u0 + tid), U, nb, &iu);
        ius[tid] = iu;
        #pragma unroll
        for (int l = 0; l < 4; l++) nub[tid][(iu + l) & 3] = nb[l];
    }
    __syncthreads();

    // ---- window bounds: spans are monotone nondecreasing in t ----
    const int mlo = ius[0];
    int nrows = ius[TILE_U - 1] + DEG - mlo + 1;
    if (nrows > WROWS) nrows = WROWS;     // safety clamp (never hit here)

    // ---- cooperative compact window load: nrows*64 float4 (<= 3/thread) ----
    for (int idx = tid; idx < nrows * NC; idx += 256) {
        win[idx] = ctrl[((size_t)b * MC + mlo) * NC + idx];
    }
    __syncthreads();

    // ---- sliding-window evaluation over 8 u rows ----
    float3 S0, S1, S2, S3;                // ring slots, slot = m & 3
    int mtop = mlo - 1;                   // highest m with S computed

    float* op = out + (((size_t)(b * OUTN + u0) * OUTN) + tid) * 3;

    #pragma unroll 1
    for (int uu = 0; uu < TILE_U; uu++) {
        const int iu0 = ius[uu];
        if (mtop < iu0 - 1 || mtop > iu0 + 3) mtop = iu0 - 1;  // safety reseed
        while (mtop < iu0 + 3) {
            mtop++;
            const float4* wrow = &win[(mtop - mlo) * NC + iv0];
            const float4 c0v = wrow[0], c1v = wrow[1], c2v = wrow[2], c3v = wrow[3];
            float sx = fmaf(nv0, c0v.x, fmaf(nv1, c1v.x, fmaf(nv2, c2v.x, nv3 * c3v.x)));
            float sy = fmaf(nv0, c0v.y, fmaf(nv1, c1v.y, fmaf(nv2, c2v.y, nv3 * c3v.y)));
            float sz = fmaf(nv0, c0v.z, fmaf(nv1, c1v.z, fmaf(nv2, c2v.z, nv3 * c3v.z)));
            const int slot = mtop & 3;
            if      (slot == 0) S0 = make_float3(sx, sy, sz);
            else if (slot == 1) S1 = make_float3(sx, sy, sz);
            else if (slot == 2) S2 = make_float3(sx, sy, sz);
            else                S3 = make_float3(sx, sy, sz);
        }

        // slot-direct pre-rotated weights: no index arithmetic
        const float w0 = nub[uu][0];
        const float w1 = nub[uu][1];
        const float w2 = nub[uu][2];
        const float w3 = nub[uu][3];

        op[0] = fmaf(w0, S0.x, fmaf(w1, S1.x, fmaf(w2, S2.x, w3 * S3.x)));
        op[1] = fmaf(w0, S0.y, fmaf(w1, S1.y, fmaf(w2, S2.y, w3 * S3.y)));
        op[2] = fmaf(w0, S0.z, fmaf(w1, S1.z, fmaf(w2, S2.z, w3 * S3.z)));
        op += OUTN * 3;
    }
}

// ---------------------------------------------------------------------------
extern "C" void kernel_launch(void* const* d_in, const int* in_sizes, int n_in,
                              void* d_out, int out_size)
{
    const float4* ctrl   = (const float4*)d_in[0];   // [16,64,64,4] f32
    const float*  knot_u = (const float*)d_in[1];    // [16,68] f32
    // d_in[2] (knot_v) unused: reference builds V from knot_u
    float* out = (float*)d_out;                      // [16,256,256,3] f32

    dim3 grid(OUTN / TILE_U, BSZ);                   // 32 x 16 = 512 blocks
    surfeval_fused<<<grid, 256>>>(ctrl, knot_u, out);
}